// round 14
// baseline (speedup 1.0000x reference)
#include <cuda_runtime.h>
#include <cuda_fp16.h>
#include <cuda.h>
#include <cstdint>

#define EPSV 1e-5f
#define QSCALE (0.0625f * 1.44269504088896340736f)   // 1/sqrt(256) * log2(e)

// ---------------- scratch ----------------
__device__ __half g_Wh[768 * 256];
__device__ float  g_bp[768];
__device__ __half g_Woh[256 * 256];
__device__ __half g_qkvh[16 * 768 * 1024];   // [b][o][p] fp16
__device__ __half g_avh[16 * 256 * 1024];    // [b][c][p] fp16

// ---------------- helpers ----------------
__device__ __forceinline__ void mma_f16(float c[4], const unsigned a[4],
                                        unsigned b0, unsigned b1) {
    asm volatile("mma.sync.aligned.m16n8k16.row.col.f32.f16.f16.f32 "
                 "{%0,%1,%2,%3}, {%4,%5,%6,%7}, {%8,%9}, {%0,%1,%2,%3};"
                 : "+f"(c[0]), "+f"(c[1]), "+f"(c[2]), "+f"(c[3])
                 : "r"(a[0]), "r"(a[1]), "r"(a[2]), "r"(a[3]), "r"(b0), "r"(b1));
}
__device__ __forceinline__ unsigned packh2(float lo, float hi) {
    unsigned d; asm("cvt.rn.f16x2.f32 %0, %1, %2;" : "=r"(d) : "f"(hi), "f"(lo)); return d;
}
__device__ __forceinline__ unsigned h2exp2(unsigned x) {
    unsigned r; asm("ex2.approx.f16x2 %0, %1;" : "=r"(r) : "r"(x)); return r;
}
__device__ __forceinline__ unsigned h2add(unsigned a, unsigned b) {
    unsigned r; asm("add.f16x2 %0, %1, %2;" : "=r"(r) : "r"(a), "r"(b)); return r;
}
__device__ __forceinline__ void cp16(uint32_t dst, const void* src) {
    asm volatile("cp.async.cg.shared.global [%0], [%1], 16;" :: "r"(dst), "l"(src));
}
__device__ __forceinline__ void cp_commit() { asm volatile("cp.async.commit_group;"); }
template<int N> __device__ __forceinline__ void cp_wait() {
    asm volatile("cp.async.wait_group %0;" :: "n"(N));
}
__device__ __forceinline__ void ldsm_x4t(unsigned& d0, unsigned& d1,
                                         unsigned& d2, unsigned& d3, uint32_t addr) {
    asm volatile("ldmatrix.sync.aligned.m8n8.x4.trans.shared.b16 {%0,%1,%2,%3}, [%4];"
                 : "=r"(d0), "=r"(d1), "=r"(d2), "=r"(d3) : "r"(addr));
}
__device__ __forceinline__ void ldsm_x4(unsigned& d0, unsigned& d1,
                                        unsigned& d2, unsigned& d3, uint32_t addr) {
    asm volatile("ldmatrix.sync.aligned.m8n8.x4.shared.b16 {%0,%1,%2,%3}, [%4];"
                 : "=r"(d0), "=r"(d1), "=r"(d2), "=r"(d3) : "r"(addr));
}
__device__ __forceinline__ void mbar_init(uint32_t a, unsigned cnt) {
    asm volatile("mbarrier.init.shared.b64 [%0], %1;" :: "r"(a), "r"(cnt) : "memory");
}
__device__ __forceinline__ void mbar_expect(uint32_t a, unsigned bytes) {
    asm volatile("mbarrier.arrive.expect_tx.shared.b64 _, [%0], %1;" :: "r"(a), "r"(bytes) : "memory");
}
__device__ __forceinline__ void mbar_wait(uint32_t a, unsigned par) {
    unsigned done;
    asm volatile("{\n\t.reg .pred p;\n\t"
                 "mbarrier.try_wait.parity.acquire.cta.shared::cta.b64 p, [%1], %2;\n\t"
                 "selp.b32 %0, 1, 0, p;\n\t}" : "=r"(done) : "r"(a), "r"(par) : "memory");
    if (!done) {
        asm volatile("{\n\t.reg .pred P1;\n\t"
                     "WL%=:\n\t"
                     "mbarrier.try_wait.parity.acquire.cta.shared::cta.b64 P1, [%0], %1, 0x989680;\n\t"
                     "@P1 bra.uni WD%=;\n\t"
                     "bra.uni WL%=;\n\t"
                     "WD%=:\n\t}" :: "r"(a), "r"(par) : "memory");
    }
}
__device__ __forceinline__ void tma3d(uint32_t dst, const void* map,
                                      int x, int y, int z, uint32_t mbar) {
    asm volatile("cp.async.bulk.tensor.3d.shared::cta.global.tile.mbarrier::complete_tx::bytes "
                 "[%0], [%1, {%2, %3, %4}], [%5];"
                 :: "r"(dst), "l"(map), "r"(x), "r"(y), "r"(z), "r"(mbar) : "memory");
}

// ---------------- prep ----------------
__global__ void prep_k(const float* __restrict__ qkv_w, const float* __restrict__ qkv_b,
                       const float* __restrict__ gamma, const float* __restrict__ beta,
                       const float* __restrict__ mean,  const float* __restrict__ var,
                       const float* __restrict__ out_w) {
    if (blockIdx.x >= 768) {
        int i = (blockIdx.x - 768) * 256 + threadIdx.x;
        g_Woh[i] = __float2half(out_w[i]);
        return;
    }
    int o = blockIdx.x;
    int c = threadIdx.x;
    float sc = gamma[c] * rsqrtf(var[c] + EPSV);
    float sh = beta[c] - mean[c] * sc;
    float w = qkv_w[o * 256 + c];
    float qsc = ((o % 192) < 64) ? QSCALE : 1.f;
    g_Wh[o * 256 + c] = __float2half(w * sc * qsc);
    float part = w * sh;
    __shared__ float red[8];
    #pragma unroll
    for (int m = 16; m > 0; m >>= 1) part += __shfl_xor_sync(0xffffffffu, part, m);
    if ((c & 31) == 0) red[c >> 5] = part;
    __syncthreads();
    if (c < 8) {
        float v = red[c];
        #pragma unroll
        for (int m = 4; m > 0; m >>= 1) v += __shfl_xor_sync(0xffu, v, m);
        if (c == 0) g_bp[o] = (qkv_b[o] + v) * qsc;
    }
}

// ---------------- X-resident fp16 GEMM (R12, best known) ----------------
#define GX_STR 136
#define GX_SZ  (256 * GX_STR)
#define GW_STG (128 * 40)
#define GH_SMEM_BYTES ((GX_SZ + 4 * GW_STG) * 2)

__global__ void __launch_bounds__(256, 2) gemm_h(const __half* __restrict__ W,
                                                 const float* __restrict__ bias,
                                                 const float* __restrict__ Xf,
                                                 const __half* __restrict__ Xh,
                                                 __half* __restrict__ Yh,
                                                 float* __restrict__ Yf,
                                                 const float* __restrict__ resid,
                                                 int M) {
    extern __shared__ __half sg[];
    __half* Xs = sg;
    uint32_t xsb = (uint32_t)__cvta_generic_to_shared(Xs);
    uint32_t wsb = xsb + (uint32_t)GX_SZ * 2;

    int tid = threadIdx.x;
    int w = tid >> 5, lane = tid & 31, r = lane >> 2, ql = lane & 3;
    int wm = w >> 1, wn = w & 1;
    int pbase = blockIdx.x * 128, b = blockIdx.z;
    const int L = M >> 8;
    const int NIT = 8 * L;

    int g = lane >> 3, jj = lane & 7;
    uint32_t x_rp = (uint32_t)((((g & 1) * 8 + jj) * GX_STR + (g >> 1) * 8) * 2);
    uint32_t w_rp = (uint32_t)(((lane & 15) * 40 + (lane >> 4) * 8) * 2);

    auto w_load = [&](int m) {
        int ob = (blockIdx.y * L + (m >> 3)) * 128;
        int kc = (m & 7) * 32;
        uint32_t sb = wsb + (uint32_t)((m & 3) * GW_STG) * 2;
        #pragma unroll
        for (int it = tid; it < 512; it += 256) {
            int o = it >> 2, f8 = it & 3;
            cp16(sb + (uint32_t)(o * 40 + f8 * 8) * 2,
                 W + (size_t)(ob + o) * 256 + kc + f8 * 8);
        }
    };

    if (Xf) {
        cp_commit();
        const float* Xb = Xf + (size_t)b * 256 * 1024;
        #pragma unroll 4
        for (int it = tid; it < 8192; it += 256) {
            int c = it >> 5, p4 = it & 31;
            float4 v = *(const float4*)&Xb[c * 1024 + pbase + p4 * 4];
            uint2 u = make_uint2(packh2(v.x, v.y), packh2(v.z, v.w));
            *(uint2*)&Xs[c * GX_STR + p4 * 4] = u;
        }
    } else {
        const __half* Xb = Xh + (size_t)b * 256 * 1024;
        #pragma unroll 4
        for (int it = tid; it < 4096; it += 256) {
            int c = it >> 4, f8 = it & 15;
            cp16(xsb + (uint32_t)(c * GX_STR + f8 * 8) * 2,
                 Xb + (size_t)c * 1024 + pbase + f8 * 8);
        }
        cp_commit();
    }
    w_load(0); cp_commit();
    w_load(1); cp_commit();
    w_load(2); cp_commit();

    float acc[2][8][4];
    #pragma unroll
    for (int t = 0; t < 2; t++)
        #pragma unroll
        for (int nb = 0; nb < 8; nb++)
            #pragma unroll
            for (int j = 0; j < 4; j++) acc[t][nb][j] = 0.f;

    const int orow = wm * 32, ncol = wn * 64;

    for (int m = 0; m < NIT; m++) {
        cp_wait<2>();
        __syncthreads();

        uint32_t sbc = wsb + (uint32_t)((m & 3) * GW_STG) * 2;
        int ki = m & 7;
        #pragma unroll
        for (int kk = 0; kk < 2; kk++) {
            unsigned a[2][4];
            #pragma unroll
            for (int t = 0; t < 2; t++)
                ldsm_x4(a[t][0], a[t][1], a[t][2], a[t][3],
                        sbc + (uint32_t)(((orow + t * 16) * 40 + kk * 16) * 2) + w_rp);
            #pragma unroll
            for (int nb2 = 0; nb2 < 8; nb2 += 2) {
                unsigned d0, d1, d2, d3;
                ldsm_x4t(d0, d1, d2, d3,
                         xsb + (uint32_t)(((ki * 32 + kk * 16) * GX_STR + ncol + nb2 * 8) * 2) + x_rp);
                mma_f16(acc[0][nb2],     a[0], d0, d1);
                mma_f16(acc[1][nb2],     a[1], d0, d1);
                mma_f16(acc[0][nb2 + 1], a[0], d2, d3);
                mma_f16(acc[1][nb2 + 1], a[1], d2, d3);
            }
        }

        if (m + 3 < NIT) w_load(m + 3);
        cp_commit();

        if (ki == 7) {
            int obase = (blockIdx.y * L + (m >> 3)) * 128;
            #pragma unroll
            for (int t = 0; t < 2; t++) {
                int o0 = obase + orow + t * 16 + r;
                float bv0 = bias[o0], bv1 = bias[o0 + 8];
                #pragma unroll
                for (int nb = 0; nb < 8; nb++) {
                    int col = pbase + ncol + nb * 8 + 2 * ql;
                    size_t i0 = ((size_t)b * M + o0) * 1024 + col;
                    size_t i1 = ((size_t)b * M + o0 + 8) * 1024 + col;
                    if (Yh) {
                        *(unsigned*)&Yh[i0] = packh2(acc[t][nb][0] + bv0, acc[t][nb][1] + bv0);
                        *(unsigned*)&Yh[i1] = packh2(acc[t][nb][2] + bv1, acc[t][nb][3] + bv1);
                    } else {
                        float2 r0 = *(const float2*)&resid[i0];
                        float2 r1 = *(const float2*)&resid[i1];
                        *(float2*)&Yf[i0] = make_float2(acc[t][nb][0] + bv0 + r0.x,
                                                        acc[t][nb][1] + bv0 + r0.y);
                        *(float2*)&Yf[i1] = make_float2(acc[t][nb][2] + bv1 + r1.x,
                                                        acc[t][nb][3] + bv1 + r1.y);
                    }
                    acc[t][nb][0] = acc[t][nb][1] = acc[t][nb][2] = acc[t][nb][3] = 0.f;
                }
            }
        }
    }
}

// ---------------- flash attention: TMA K/V, 3 CTAs/SM, interleaved softmax ----------------
// q-tile 128, grid (8, 4, 16), block 128 (4 warps x 32 q-rows).
// Q frags reloaded per tile via ldmatrix from stationary Q stage (register diet).
#define FT_STAGE 16384
#define FT_QOFF  49152
#define FT_QSTR  136
#define FT_ONES  66560
#define FT_MBAR  67712
#define FH_SMEM_BYTES (67744 + 1024)

__global__ void __launch_bounds__(128, 3) flash_h(const __half* __restrict__ qkv,
                                                  __half* __restrict__ av,
                                                  const __grid_constant__ CUtensorMap tmap) {
    extern __shared__ __half sh[];
    uint32_t usb = (uint32_t)__cvta_generic_to_shared(sh);
    uint32_t kvb = (usb + 1023u) & ~1023u;
    __half* shA = (__half*)((char*)sh + (kvb - usb));

    int tid = threadIdx.x;
    int w = tid >> 5, lane = tid & 31, r = lane >> 2, ql = lane & 3;
    int qb = blockIdx.x * 128;
    int h  = blockIdx.y;
    int b  = blockIdx.z;

    const size_t hb = ((size_t)b * 768 + (size_t)h * 192) * 1024;
    const __half* Qg = qkv + hb;
    const int yK = h * 192 + 64;
    const int yV = h * 192 + 128;

    if (tid == 0) {
        #pragma unroll
        for (int s = 0; s < 3; s++) mbar_init(kvb + FT_MBAR + s * 8, 1);
    }
    __half* shO = shA + FT_ONES / 2;
    for (int idx = tid; idx < 8 * 72; idx += 128)
        shO[idx] = __ushort_as_half((unsigned short)((idx < 72) ? 0x3C00 : 0));
    uint32_t qsb = kvb + FT_QOFF;
    #pragma unroll
    for (int idx = tid; idx < 1024; idx += 128) {
        int c = idx >> 4, f8 = idx & 15;
        cp16(qsb + (uint32_t)(c * FT_QSTR + f8 * 8) * 2, Qg + (size_t)c * 1024 + qb + f8 * 8);
    }
    cp_commit();
    __syncthreads();

    if (tid == 0) {
        asm volatile("fence.proxy.async.shared::cta;" ::: "memory");
        #pragma unroll
        for (int s = 0; s < 2; s++) {
            uint32_t mb = kvb + FT_MBAR + s * 8;
            mbar_expect(mb, FT_STAGE);
            tma3d(kvb + s * FT_STAGE,        &tmap, s * 64, yK, b, mb);
            tma3d(kvb + s * FT_STAGE + 8192, &tmap, s * 64, yV, b, mb);
        }
    }

    cp_wait<0>();
    __syncthreads();

    const int qrow = w * 32;
    int g = lane >> 3, jj = lane & 7;
    int g1 = g & 1, g2 = g >> 1;
    uint32_t q_rp = (uint32_t)(((g2 * 8 + jj) * FT_QSTR + g1 * 8) * 2);
    uint32_t rbK = (uint32_t)((g1 * 8 + jj) * 128);
    uint32_t rbV = (uint32_t)((g2 * 8 + jj) * 128);
    unsigned oc0 = *(const unsigned*)&shO[r * 72 + 2 * ql];
    unsigned oc1 = *(const unsigned*)&shO[r * 72 + 2 * ql + 8];

    float O[2][8][4], O9[2][4];
    #pragma unroll
    for (int t = 0; t < 2; t++) {
        #pragma unroll
        for (int nb = 0; nb < 8; nb++)
            #pragma unroll
            for (int j = 0; j < 4; j++) O[t][nb][j] = 0.f;
        #pragma unroll
        for (int j = 0; j < 4; j++) O9[t][j] = 0.f;
    }

    for (int kt = 0; kt < 16; kt++) {
        int s = kt % 3;
        mbar_wait(kvb + FT_MBAR + s * 8, (unsigned)((kt / 3) & 1));
        __syncthreads();

        if (tid == 0 && kt + 2 < 16) {
            int s2 = (kt + 2) % 3;
            uint32_t mb = kvb + FT_MBAR + s2 * 8;
            mbar_expect(mb, FT_STAGE);
            tma3d(kvb + s2 * FT_STAGE,        &tmap, (kt + 2) * 64, yK, b, mb);
            tma3d(kvb + s2 * FT_STAGE + 8192, &tmap, (kt + 2) * 64, yV, b, mb);
        }

        uint32_t kcur = kvb + s * FT_STAGE;
        uint32_t vcur = kcur + 8192;

        #pragma unroll
        for (int t = 0; t < 2; t++) {
            int q0b = qrow + t * 16;

            // ---- S = Q K^T (Q frags reloaded from stationary stage) ----
            float S[8][4];
            #pragma unroll
            for (int nb = 0; nb < 8; nb++)
                #pragma unroll
                for (int j = 0; j < 4; j++) S[nb][j] = 0.f;

            #pragma unroll
            for (int kk = 0; kk < 4; kk++) {
                unsigned qa[4];
                ldsm_x4t(qa[0], qa[1], qa[2], qa[3],
                         qsb + (uint32_t)((kk * 16 * FT_QSTR + q0b) * 2) + q_rp);
                #pragma unroll
                for (int nb2 = 0; nb2 < 8; nb2 += 2) {
                    unsigned d0, d1, d2, d3;
                    ldsm_x4t(d0, d1, d2, d3,
                             kcur + (uint32_t)(kk * 2048) + rbK
                                  + ((uint32_t)((nb2 + g2) ^ jj) << 4));
                    mma_f16(S[nb2],     qa, d0, d1);
                    mma_f16(S[nb2 + 1], qa, d2, d3);
                }
            }

            // ---- interleaved: per kk, exp -> pack -> PV mma ----
            unsigned ps[4];
            #pragma unroll
            for (int kk = 0; kk < 4; kk++) {
                unsigned pa[4];
                pa[0] = h2exp2(packh2(S[2 * kk][0],     S[2 * kk][1]));
                pa[1] = h2exp2(packh2(S[2 * kk][2],     S[2 * kk][3]));
                pa[2] = h2exp2(packh2(S[2 * kk + 1][0], S[2 * kk + 1][1]));
                pa[3] = h2exp2(packh2(S[2 * kk + 1][2], S[2 * kk + 1][3]));
                if (kk == 0) {
                    ps[0] = pa[0]; ps[1] = pa[1]; ps[2] = pa[2]; ps[3] = pa[3];
                } else {
                    ps[0] = h2add(ps[0], pa[0]); ps[1] = h2add(ps[1], pa[1]);
                    ps[2] = h2add(ps[2], pa[2]); ps[3] = h2add(ps[3], pa[3]);
                }
                #pragma unroll
                for (int nb2 = 0; nb2 < 8; nb2 += 2) {
                    unsigned e0, e1, e2, e3;
                    ldsm_x4(e0, e1, e2, e3,
                            vcur + (uint32_t)(nb2 * 1024) + rbV
                                 + ((uint32_t)((kk * 2 + g1) ^ jj) << 4));
                    mma_f16(O[t][nb2],     pa, e0, e1);
                    mma_f16(O[t][nb2 + 1], pa, e2, e3);
                }
            }
            mma_f16(O9[t], ps, oc0, oc1);
        }
    }

    unsigned short* Uw = (unsigned short*)(shA + FT_QOFF / 2);
    __syncthreads();   // all warps done with Q stage before overwrite
    #pragma unroll
    for (int t = 0; t < 2; t++) {
        float l0 = __shfl_sync(0xffffffffu, O9[t][0], lane & 28);
        float l1 = __shfl_sync(0xffffffffu, O9[t][2], lane & 28);
        float inv0 = 1.f / l0, inv1 = 1.f / l1;
        int q0 = qrow + t * 16 + r;
        #pragma unroll
        for (int nb = 0; nb < 8; nb++) {
            int c = nb * 8 + 2 * ql;
            Uw[c * FT_QSTR + q0]           = __half_as_ushort(__float2half(O[t][nb][0] * inv0));
            Uw[(c + 1) * FT_QSTR + q0]     = __half_as_ushort(__float2half(O[t][nb][1] * inv0));
            Uw[c * FT_QSTR + q0 + 8]       = __half_as_ushort(__float2half(O[t][nb][2] * inv1));
            Uw[(c + 1) * FT_QSTR + q0 + 8] = __half_as_ushort(__float2half(O[t][nb][3] * inv1));
        }
    }
    __syncthreads();

    size_t ob = ((size_t)b * 256 + (size_t)h * 64) * 1024 + qb;
    for (int idx = tid; idx < 64 * 64; idx += 128) {
        int c = idx >> 6, wd = idx & 63;
        *(unsigned*)&av[ob + (size_t)c * 1024 + wd * 2] =
            ((unsigned*)(shA + FT_QOFF / 2))[c * (FT_QSTR / 2) + wd];
    }
}

// ---------------- launcher ----------------
extern "C" void kernel_launch(void* const* d_in, const int* in_sizes, int n_in,
                              void* d_out, int out_size) {
    const float* x      = (const float*)d_in[0];
    const float* gamma  = (const float*)d_in[1];
    const float* beta   = (const float*)d_in[2];
    const float* rmean  = (const float*)d_in[3];
    const float* rvar   = (const float*)d_in[4];
    const float* qkv_w  = (const float*)d_in[5];
    const float* qkv_b  = (const float*)d_in[6];
    const float* out_w  = (const float*)d_in[7];
    const float* out_b  = (const float*)d_in[8];

    float* bp;
    __half *Wh, *Woh, *qkvh, *avh;
    cudaGetSymbolAddress((void**)&Wh,   g_Wh);
    cudaGetSymbolAddress((void**)&bp,   g_bp);
    cudaGetSymbolAddress((void**)&Woh,  g_Woh);
    cudaGetSymbolAddress((void**)&qkvh, g_qkvh);
    cudaGetSymbolAddress((void**)&avh,  g_avh);

    // tensormap over qkvh: dims {p=1024, o=768, b=16}, box {64, 64, 1}, SW128
    static CUtensorMap tmap;
    {
        typedef CUresult (*EncFn)(CUtensorMap*, CUtensorMapDataType, cuuint32_t, void*,
                                  const cuuint64_t*, const cuuint64_t*, const cuuint32_t*,
                                  const cuuint32_t*, CUtensorMapInterleave, CUtensorMapSwizzle,
                                  CUtensorMapL2promotion, CUtensorMapFloatOOBfill);
        static EncFn enc = nullptr;
        if (!enc) {
            void* fn = nullptr;
            cudaDriverEntryPointQueryResult qr;
            cudaGetDriverEntryPointByVersion("cuTensorMapEncodeTiled", &fn, 12000,
                                             cudaEnableDefault, &qr);
            enc = (EncFn)fn;
        }
        cuuint64_t dims[3]    = {1024, 768, 16};
        cuuint64_t strides[2] = {2048, 768ull * 2048ull};
        cuuint32_t box[3]     = {64, 64, 1};
        cuuint32_t estr[3]    = {1, 1, 1};
        enc(&tmap, CU_TENSOR_MAP_DATA_TYPE_UINT16, 3, qkvh, dims, strides, box, estr,
            CU_TENSOR_MAP_INTERLEAVE_NONE, CU_TENSOR_MAP_SWIZZLE_128B,
            CU_TENSOR_MAP_L2_PROMOTION_L2_128B, CU_TENSOR_MAP_FLOAT_OOB_FILL_NONE);
    }

    cudaFuncSetAttribute(gemm_h,  cudaFuncAttributeMaxDynamicSharedMemorySize, GH_SMEM_BYTES);
    cudaFuncSetAttribute(flash_h, cudaFuncAttributeMaxDynamicSharedMemorySize, FH_SMEM_BYTES);

    prep_k<<<1024, 256>>>(qkv_w, qkv_b, gamma, beta, rmean, rvar, out_w);
    gemm_h<<<dim3(8, 2, 16), 256, GH_SMEM_BYTES>>>(Wh, bp, x, nullptr, qkvh, nullptr, nullptr, 768);
    flash_h<<<dim3(8, 4, 16), 128, FH_SMEM_BYTES>>>(qkvh, avh, tmap);
    gemm_h<<<dim3(8, 2, 16), 256, GH_SMEM_BYTES>>>(Woh, out_b, nullptr, avh, nullptr, (float*)d_out, x, 256);
}

// round 15
// speedup vs baseline: 1.1079x; 1.1079x over previous
#include <cuda_runtime.h>
#include <cuda_fp16.h>
#include <cuda.h>
#include <cstdint>

#define EPSV 1e-5f
#define QSCALE (0.0625f * 1.44269504088896340736f)   // 1/sqrt(256) * log2(e)

// ---------------- scratch ----------------
__device__ __half g_Wh[768 * 256];
__device__ float  g_bp[768];
__device__ __half g_Woh[256 * 256];
__device__ __half g_qkvh[16 * 768 * 1024];   // [b][o][p] fp16
__device__ __half g_avh[16 * 256 * 1024];    // [b][c][p] fp16

// ---------------- helpers ----------------
__device__ __forceinline__ void mma_f16(float c[4], const unsigned a[4],
                                        unsigned b0, unsigned b1) {
    asm volatile("mma.sync.aligned.m16n8k16.row.col.f32.f16.f16.f32 "
                 "{%0,%1,%2,%3}, {%4,%5,%6,%7}, {%8,%9}, {%0,%1,%2,%3};"
                 : "+f"(c[0]), "+f"(c[1]), "+f"(c[2]), "+f"(c[3])
                 : "r"(a[0]), "r"(a[1]), "r"(a[2]), "r"(a[3]), "r"(b0), "r"(b1));
}
__device__ __forceinline__ unsigned packh2(float lo, float hi) {
    unsigned d; asm("cvt.rn.f16x2.f32 %0, %1, %2;" : "=r"(d) : "f"(hi), "f"(lo)); return d;
}
__device__ __forceinline__ unsigned h2exp2(unsigned x) {
    unsigned r; asm("ex2.approx.f16x2 %0, %1;" : "=r"(r) : "r"(x)); return r;
}
__device__ __forceinline__ unsigned h2add(unsigned a, unsigned b) {
    unsigned r; asm("add.f16x2 %0, %1, %2;" : "=r"(r) : "r"(a), "r"(b)); return r;
}
__device__ __forceinline__ void cp16(uint32_t dst, const void* src) {
    asm volatile("cp.async.cg.shared.global [%0], [%1], 16;" :: "r"(dst), "l"(src));
}
__device__ __forceinline__ void cp_commit() { asm volatile("cp.async.commit_group;"); }
template<int N> __device__ __forceinline__ void cp_wait() {
    asm volatile("cp.async.wait_group %0;" :: "n"(N));
}
__device__ __forceinline__ void ldsm_x4t(unsigned& d0, unsigned& d1,
                                         unsigned& d2, unsigned& d3, uint32_t addr) {
    asm volatile("ldmatrix.sync.aligned.m8n8.x4.trans.shared.b16 {%0,%1,%2,%3}, [%4];"
                 : "=r"(d0), "=r"(d1), "=r"(d2), "=r"(d3) : "r"(addr));
}
__device__ __forceinline__ void ldsm_x4(unsigned& d0, unsigned& d1,
                                        unsigned& d2, unsigned& d3, uint32_t addr) {
    asm volatile("ldmatrix.sync.aligned.m8n8.x4.shared.b16 {%0,%1,%2,%3}, [%4];"
                 : "=r"(d0), "=r"(d1), "=r"(d2), "=r"(d3) : "r"(addr));
}
__device__ __forceinline__ void mbar_init(uint32_t a, unsigned cnt) {
    asm volatile("mbarrier.init.shared.b64 [%0], %1;" :: "r"(a), "r"(cnt) : "memory");
}
__device__ __forceinline__ void mbar_expect(uint32_t a, unsigned bytes) {
    asm volatile("mbarrier.arrive.expect_tx.shared.b64 _, [%0], %1;" :: "r"(a), "r"(bytes) : "memory");
}
__device__ __forceinline__ void mbar_wait(uint32_t a, unsigned par) {
    unsigned done;
    asm volatile("{\n\t.reg .pred p;\n\t"
                 "mbarrier.try_wait.parity.acquire.cta.shared::cta.b64 p, [%1], %2;\n\t"
                 "selp.b32 %0, 1, 0, p;\n\t}" : "=r"(done) : "r"(a), "r"(par) : "memory");
    if (!done) {
        asm volatile("{\n\t.reg .pred P1;\n\t"
                     "WL%=:\n\t"
                     "mbarrier.try_wait.parity.acquire.cta.shared::cta.b64 P1, [%0], %1, 0x989680;\n\t"
                     "@P1 bra.uni WD%=;\n\t"
                     "bra.uni WL%=;\n\t"
                     "WD%=:\n\t}" :: "r"(a), "r"(par) : "memory");
    }
}
__device__ __forceinline__ void tma3d(uint32_t dst, const void* map,
                                      int x, int y, int z, uint32_t mbar) {
    asm volatile("cp.async.bulk.tensor.3d.shared::cta.global.tile.mbarrier::complete_tx::bytes "
                 "[%0], [%1, {%2, %3, %4}], [%5];"
                 :: "r"(dst), "l"(map), "r"(x), "r"(y), "r"(z), "r"(mbar) : "memory");
}

// ---------------- prep ----------------
__global__ void prep_k(const float* __restrict__ qkv_w, const float* __restrict__ qkv_b,
                       const float* __restrict__ gamma, const float* __restrict__ beta,
                       const float* __restrict__ mean,  const float* __restrict__ var,
                       const float* __restrict__ out_w) {
    if (blockIdx.x >= 768) {
        int i = (blockIdx.x - 768) * 256 + threadIdx.x;
        g_Woh[i] = __float2half(out_w[i]);
        return;
    }
    int o = blockIdx.x;
    int c = threadIdx.x;
    float sc = gamma[c] * rsqrtf(var[c] + EPSV);
    float sh = beta[c] - mean[c] * sc;
    float w = qkv_w[o * 256 + c];
    float qsc = ((o % 192) < 64) ? QSCALE : 1.f;
    g_Wh[o * 256 + c] = __float2half(w * sc * qsc);
    float part = w * sh;
    __shared__ float red[8];
    #pragma unroll
    for (int m = 16; m > 0; m >>= 1) part += __shfl_xor_sync(0xffffffffu, part, m);
    if ((c & 31) == 0) red[c >> 5] = part;
    __syncthreads();
    if (c < 8) {
        float v = red[c];
        #pragma unroll
        for (int m = 4; m > 0; m >>= 1) v += __shfl_xor_sync(0xffu, v, m);
        if (c == 0) g_bp[o] = (qkv_b[o] + v) * qsc;
    }
}

// ---------------- X-resident fp16 GEMM, W via TMA ----------------
// Y[b][o][p] = W[o][:] . X[b][:][p] + bias (+resid).  N=1024, K=256.
// X resident [k 256][n 128] stride 136 (one-time fill).
// W: TMA SW128 stages [128 o][64 k] = 16 KB x2, mbarrier pipeline.
#define GX_STR 136
#define GX_SZ  (256 * GX_STR * 2)    // 69632 B (1024-aligned)
#define GW_OFF GX_SZ
#define GW_STG 16384
#define GM_OFF (GW_OFF + 2 * GW_STG) // 102400
#define GH_SMEM_BYTES (GM_OFF + 64 + 1024)

__global__ void __launch_bounds__(256, 2) gemm_h(
        const __grid_constant__ CUtensorMap wmap,
        const float* __restrict__ bias,
        const float* __restrict__ Xf,
        const __half* __restrict__ Xh,
        __half* __restrict__ Yh, float* __restrict__ Yf,
        const float* __restrict__ resid, int M) {
    extern __shared__ __half sg[];
    uint32_t base0 = (uint32_t)__cvta_generic_to_shared(sg);
    uint32_t sb = (base0 + 1023u) & ~1023u;

    int tid = threadIdx.x;
    int w = tid >> 5, lane = tid & 31, r = lane >> 2, ql = lane & 3;
    int wm = w >> 1, wn = w & 1;
    int pbase = blockIdx.x * 128, b = blockIdx.z;
    const int L = M >> 8;
    const int NIT = 4 * L;           // 64-k stages

    int g = lane >> 3, jj = lane & 7;
    uint32_t x_rp = (uint32_t)((((g & 1) * 8 + jj) * GX_STR + (g >> 1) * 8) * 2);
    int rw = lane & 15, kh = lane >> 4, row7 = rw & 7;

    uint32_t mb[2] = { sb + GM_OFF, sb + GM_OFF + 8 };
    if (tid == 0) { mbar_init(mb[0], 1); mbar_init(mb[1], 1); }
    __syncthreads();
    if (tid == 0) {
        asm volatile("fence.proxy.async.shared::cta;" ::: "memory");
        // W prologue: stages 0,1 of o-block 0
        int y0 = blockIdx.y * L * 128;
        mbar_expect(mb[0], GW_STG);
        tma3d(sb + GW_OFF,          &wmap, 0,  y0, 0, mb[0]);
        mbar_expect(mb[1], GW_STG);
        tma3d(sb + GW_OFF + GW_STG, &wmap, 64, y0, 0, mb[1]);
    }

    // ---- X fill (one-time) ----
    if (Xf) {
        const float* Xb = Xf + (size_t)b * 256 * 1024;
        #pragma unroll 4
        for (int it = tid; it < 8192; it += 256) {
            int c = it >> 5, p4 = it & 31;
            float4 v = *(const float4*)&Xb[c * 1024 + pbase + p4 * 4];
            uint2 u = make_uint2(packh2(v.x, v.y), packh2(v.z, v.w));
            uint32_t a = sb + (uint32_t)(c * GX_STR + p4 * 4) * 2;
            asm volatile("st.shared.v2.b32 [%0], {%1, %2};" :: "r"(a), "r"(u.x), "r"(u.y) : "memory");
        }
    } else {
        const __half* Xb = Xh + (size_t)b * 256 * 1024;
        #pragma unroll 4
        for (int it = tid; it < 4096; it += 256) {
            int c = it >> 4, f8 = it & 15;
            cp16(sb + (uint32_t)(c * GX_STR + f8 * 8) * 2,
                 Xb + (size_t)c * 1024 + pbase + f8 * 8);
        }
        cp_commit();
        cp_wait<0>();
    }
    __syncthreads();

    float acc[2][8][4];
    #pragma unroll
    for (int t = 0; t < 2; t++)
        #pragma unroll
        for (int nb = 0; nb < 8; nb++)
            #pragma unroll
            for (int j = 0; j < 4; j++) acc[t][nb][j] = 0.f;

    const int orow = wm * 32, ncol = wn * 64;

    for (int m = 0; m < NIT; m++) {
        mbar_wait(mb[m & 1], (unsigned)((m >> 1) & 1));

        uint32_t wst = sb + GW_OFF + (uint32_t)((m & 1) * GW_STG);
        int kst = (m & 3) * 64;
        #pragma unroll
        for (int kk = 0; kk < 4; kk++) {
            unsigned a[2][4];
            #pragma unroll
            for (int t = 0; t < 2; t++) {
                int row = orow + t * 16 + rw;
                ldsm_x4(a[t][0], a[t][1], a[t][2], a[t][3],
                        wst + (uint32_t)(row * 128)
                            + ((uint32_t)(((kk * 2 + kh) ^ row7)) << 4));
            }
            #pragma unroll
            for (int nb2 = 0; nb2 < 8; nb2 += 2) {
                unsigned d0, d1, d2, d3;
                ldsm_x4t(d0, d1, d2, d3,
                         sb + (uint32_t)(((kst + kk * 16) * GX_STR + ncol + nb2 * 8) * 2) + x_rp);
                mma_f16(acc[0][nb2],     a[0], d0, d1);
                mma_f16(acc[1][nb2],     a[1], d0, d1);
                mma_f16(acc[0][nb2 + 1], a[0], d2, d3);
                mma_f16(acc[1][nb2 + 1], a[1], d2, d3);
            }
        }
        __syncthreads();

        if (tid == 0 && m + 2 < NIT) {
            int m2 = m + 2;
            mbar_expect(mb[m & 1], GW_STG);
            tma3d(wst, &wmap, (m2 & 3) * 64, (blockIdx.y * L + (m2 >> 2)) * 128, 0, mb[m & 1]);
        }

        if ((m & 3) == 3) {
            int obase = (blockIdx.y * L + (m >> 2)) * 128;
            #pragma unroll
            for (int t = 0; t < 2; t++) {
                int o0 = obase + orow + t * 16 + r;
                float bv0 = bias[o0], bv1 = bias[o0 + 8];
                #pragma unroll
                for (int nb = 0; nb < 8; nb++) {
                    int col = pbase + ncol + nb * 8 + 2 * ql;
                    size_t i0 = ((size_t)b * M + o0) * 1024 + col;
                    size_t i1 = ((size_t)b * M + o0 + 8) * 1024 + col;
                    if (Yh) {
                        *(unsigned*)&Yh[i0] = packh2(acc[t][nb][0] + bv0, acc[t][nb][1] + bv0);
                        *(unsigned*)&Yh[i1] = packh2(acc[t][nb][2] + bv1, acc[t][nb][3] + bv1);
                    } else {
                        float2 r0 = *(const float2*)&resid[i0];
                        float2 r1 = *(const float2*)&resid[i1];
                        *(float2*)&Yf[i0] = make_float2(acc[t][nb][0] + bv0 + r0.x,
                                                        acc[t][nb][1] + bv0 + r0.y);
                        *(float2*)&Yf[i1] = make_float2(acc[t][nb][2] + bv1 + r1.x,
                                                        acc[t][nb][3] + bv1 + r1.y);
                    }
                    acc[t][nb][0] = acc[t][nb][1] = acc[t][nb][2] = acc[t][nb][3] = 0.f;
                }
            }
        }
    }
}

// ---------------- flash attention (exact R12 best: TMA K/V, 2 CTAs/SM) ----------------
#define FT_STAGE 16384
#define FT_QOFF  49152
#define FT_QSTR  136
#define FT_ONES  66560
#define FT_MBAR  67712
#define FH_SMEM_BYTES (67744 + 1024)

__global__ void __launch_bounds__(128, 2) flash_h(const __half* __restrict__ qkv,
                                                  __half* __restrict__ av,
                                                  const __grid_constant__ CUtensorMap tmap) {
    extern __shared__ __half sh[];
    uint32_t usb = (uint32_t)__cvta_generic_to_shared(sh);
    uint32_t kvb = (usb + 1023u) & ~1023u;
    __half* shA = (__half*)((char*)sh + (kvb - usb));

    int tid = threadIdx.x;
    int w = tid >> 5, lane = tid & 31, r = lane >> 2, ql = lane & 3;
    int qb = blockIdx.x * 128;
    int h  = blockIdx.y;
    int b  = blockIdx.z;

    const size_t hb = ((size_t)b * 768 + (size_t)h * 192) * 1024;
    const __half* Qg = qkv + hb;
    const int yK = h * 192 + 64;
    const int yV = h * 192 + 128;

    if (tid == 0) {
        #pragma unroll
        for (int s = 0; s < 3; s++) mbar_init(kvb + FT_MBAR + s * 8, 1);
    }
    __half* shO = shA + FT_ONES / 2;
    for (int idx = tid; idx < 8 * 72; idx += 128)
        shO[idx] = __ushort_as_half((unsigned short)((idx < 72) ? 0x3C00 : 0));
    uint32_t qsb = kvb + FT_QOFF;
    #pragma unroll
    for (int idx = tid; idx < 1024; idx += 128) {
        int c = idx >> 4, f8 = idx & 15;
        cp16(qsb + (uint32_t)(c * FT_QSTR + f8 * 8) * 2, Qg + (size_t)c * 1024 + qb + f8 * 8);
    }
    cp_commit();
    __syncthreads();

    if (tid == 0) {
        asm volatile("fence.proxy.async.shared::cta;" ::: "memory");
        #pragma unroll
        for (int s = 0; s < 2; s++) {
            uint32_t mb = kvb + FT_MBAR + s * 8;
            mbar_expect(mb, FT_STAGE);
            tma3d(kvb + s * FT_STAGE,        &tmap, s * 64, yK, b, mb);
            tma3d(kvb + s * FT_STAGE + 8192, &tmap, s * 64, yV, b, mb);
        }
    }

    cp_wait<0>();
    __syncthreads();

    const int qrow = w * 32;
    const unsigned short* Uss = (const unsigned short*)(shA + FT_QOFF / 2);
    unsigned qf[2][4][4];
    #pragma unroll
    for (int t = 0; t < 2; t++)
        #pragma unroll
        for (int kk = 0; kk < 4; kk++) {
            int q0 = qrow + t * 16 + r;
            int c0 = kk * 16 + 2 * ql;
            qf[t][kk][0] = (unsigned)Uss[c0 * FT_QSTR + q0]           | ((unsigned)Uss[(c0 + 1) * FT_QSTR + q0] << 16);
            qf[t][kk][1] = (unsigned)Uss[c0 * FT_QSTR + q0 + 8]       | ((unsigned)Uss[(c0 + 1) * FT_QSTR + q0 + 8] << 16);
            qf[t][kk][2] = (unsigned)Uss[(c0 + 8) * FT_QSTR + q0]     | ((unsigned)Uss[(c0 + 9) * FT_QSTR + q0] << 16);
            qf[t][kk][3] = (unsigned)Uss[(c0 + 8) * FT_QSTR + q0 + 8] | ((unsigned)Uss[(c0 + 9) * FT_QSTR + q0 + 8] << 16);
        }

    int g = lane >> 3, jj = lane & 7;
    int g1 = g & 1, g2 = g >> 1;
    uint32_t rbK = (uint32_t)((g1 * 8 + jj) * 128);
    uint32_t rbV = (uint32_t)((g2 * 8 + jj) * 128);
    unsigned oc0 = *(const unsigned*)&shO[r * 72 + 2 * ql];
    unsigned oc1 = *(const unsigned*)&shO[r * 72 + 2 * ql + 8];

    float O[2][8][4], O9[2][4];
    #pragma unroll
    for (int t = 0; t < 2; t++) {
        #pragma unroll
        for (int nb = 0; nb < 8; nb++)
            #pragma unroll
            for (int j = 0; j < 4; j++) O[t][nb][j] = 0.f;
        #pragma unroll
        for (int j = 0; j < 4; j++) O9[t][j] = 0.f;
    }

    for (int kt = 0; kt < 16; kt++) {
        int s = kt % 3;
        mbar_wait(kvb + FT_MBAR + s * 8, (unsigned)((kt / 3) & 1));
        __syncthreads();

        if (tid == 0 && kt + 2 < 16) {
            int s2 = (kt + 2) % 3;
            uint32_t mb = kvb + FT_MBAR + s2 * 8;
            mbar_expect(mb, FT_STAGE);
            tma3d(kvb + s2 * FT_STAGE,        &tmap, (kt + 2) * 64, yK, b, mb);
            tma3d(kvb + s2 * FT_STAGE + 8192, &tmap, (kt + 2) * 64, yV, b, mb);
        }

        uint32_t kcur = kvb + s * FT_STAGE;
        uint32_t vcur = kcur + 8192;

        #pragma unroll
        for (int t = 0; t < 2; t++) {
            float S[8][4];
            #pragma unroll
            for (int nb = 0; nb < 8; nb++)
                #pragma unroll
                for (int j = 0; j < 4; j++) S[nb][j] = 0.f;

            #pragma unroll
            for (int kk = 0; kk < 4; kk++) {
                #pragma unroll
                for (int nb2 = 0; nb2 < 8; nb2 += 2) {
                    unsigned d0, d1, d2, d3;
                    ldsm_x4t(d0, d1, d2, d3,
                             kcur + (uint32_t)(kk * 2048) + rbK
                                  + ((uint32_t)((nb2 + g2) ^ jj) << 4));
                    mma_f16(S[nb2],     qf[t][kk], d0, d1);
                    mma_f16(S[nb2 + 1], qf[t][kk], d2, d3);
                }
            }

            unsigned pa[4][4];
            #pragma unroll
            for (int kk = 0; kk < 4; kk++) {
                pa[kk][0] = h2exp2(packh2(S[2 * kk][0],     S[2 * kk][1]));
                pa[kk][1] = h2exp2(packh2(S[2 * kk][2],     S[2 * kk][3]));
                pa[kk][2] = h2exp2(packh2(S[2 * kk + 1][0], S[2 * kk + 1][1]));
                pa[kk][3] = h2exp2(packh2(S[2 * kk + 1][2], S[2 * kk + 1][3]));
            }

            #pragma unroll
            for (int kk = 0; kk < 4; kk++) {
                #pragma unroll
                for (int nb2 = 0; nb2 < 8; nb2 += 2) {
                    unsigned e0, e1, e2, e3;
                    ldsm_x4(e0, e1, e2, e3,
                            vcur + (uint32_t)(nb2 * 1024) + rbV
                                 + ((uint32_t)((kk * 2 + g1) ^ jj) << 4));
                    mma_f16(O[t][nb2],     pa[kk], e0, e1);
                    mma_f16(O[t][nb2 + 1], pa[kk], e2, e3);
                }
            }
            unsigned ps[4];
            #pragma unroll
            for (int j = 0; j < 4; j++)
                ps[j] = h2add(h2add(pa[0][j], pa[1][j]), h2add(pa[2][j], pa[3][j]));
            mma_f16(O9[t], ps, oc0, oc1);
        }
    }

    unsigned short* Uw = (unsigned short*)(shA + FT_QOFF / 2);
    #pragma unroll
    for (int t = 0; t < 2; t++) {
        float l0 = __shfl_sync(0xffffffffu, O9[t][0], lane & 28);
        float l1 = __shfl_sync(0xffffffffu, O9[t][2], lane & 28);
        float inv0 = 1.f / l0, inv1 = 1.f / l1;
        int q0 = qrow + t * 16 + r;
        #pragma unroll
        for (int nb = 0; nb < 8; nb++) {
            int c = nb * 8 + 2 * ql;
            Uw[c * FT_QSTR + q0]           = __half_as_ushort(__float2half(O[t][nb][0] * inv0));
            Uw[(c + 1) * FT_QSTR + q0]     = __half_as_ushort(__float2half(O[t][nb][1] * inv0));
            Uw[c * FT_QSTR + q0 + 8]       = __half_as_ushort(__float2half(O[t][nb][2] * inv1));
            Uw[(c + 1) * FT_QSTR + q0 + 8] = __half_as_ushort(__float2half(O[t][nb][3] * inv1));
        }
    }
    __syncthreads();

    size_t ob = ((size_t)b * 256 + (size_t)h * 64) * 1024 + qb;
    for (int idx = tid; idx < 64 * 64; idx += 128) {
        int c = idx >> 6, wd = idx & 63;
        *(unsigned*)&av[ob + (size_t)c * 1024 + wd * 2] =
            ((unsigned*)(shA + FT_QOFF / 2))[c * (FT_QSTR / 2) + wd];
    }
}

// ---------------- launcher ----------------
typedef CUresult (*EncFn)(CUtensorMap*, CUtensorMapDataType, cuuint32_t, void*,
                          const cuuint64_t*, const cuuint64_t*, const cuuint32_t*,
                          const cuuint32_t*, CUtensorMapInterleave, CUtensorMapSwizzle,
                          CUtensorMapL2promotion, CUtensorMapFloatOOBfill);
static EncFn get_enc() {
    static EncFn enc = nullptr;
    if (!enc) {
        void* fn = nullptr;
        cudaDriverEntryPointQueryResult qr;
        cudaGetDriverEntryPointByVersion("cuTensorMapEncodeTiled", &fn, 12000,
                                         cudaEnableDefault, &qr);
        enc = (EncFn)fn;
    }
    return enc;
}
static void enc3(CUtensorMap* m, void* p, cuuint64_t d0, cuuint64_t d1, cuuint64_t d2,
                 cuuint64_t s1b, cuuint64_t s2b, cuuint32_t b0, cuuint32_t b1) {
    cuuint64_t dims[3] = {d0, d1, d2};
    cuuint64_t str[2] = {s1b, s2b};
    cuuint32_t box[3] = {b0, b1, 1};
    cuuint32_t est[3] = {1, 1, 1};
    get_enc()(m, CU_TENSOR_MAP_DATA_TYPE_UINT16, 3, p, dims, str, box, est,
              CU_TENSOR_MAP_INTERLEAVE_NONE, CU_TENSOR_MAP_SWIZZLE_128B,
              CU_TENSOR_MAP_L2_PROMOTION_L2_128B, CU_TENSOR_MAP_FLOAT_OOB_FILL_NONE);
}

extern "C" void kernel_launch(void* const* d_in, const int* in_sizes, int n_in,
                              void* d_out, int out_size) {
    const float* x      = (const float*)d_in[0];
    const float* gamma  = (const float*)d_in[1];
    const float* beta   = (const float*)d_in[2];
    const float* rmean  = (const float*)d_in[3];
    const float* rvar   = (const float*)d_in[4];
    const float* qkv_w  = (const float*)d_in[5];
    const float* qkv_b  = (const float*)d_in[6];
    const float* out_w  = (const float*)d_in[7];
    const float* out_b  = (const float*)d_in[8];

    float* bp;
    __half *Wh, *Woh, *qkvh, *avh;
    cudaGetSymbolAddress((void**)&Wh,   g_Wh);
    cudaGetSymbolAddress((void**)&bp,   g_bp);
    cudaGetSymbolAddress((void**)&Woh,  g_Woh);
    cudaGetSymbolAddress((void**)&qkvh, g_qkvh);
    cudaGetSymbolAddress((void**)&avh,  g_avh);

    static CUtensorMap tmap, wmapQ, wmapO;
    enc3(&tmap,  qkvh, 1024, 768, 16, 2048, 768ull * 2048ull, 64, 64);   // flash K/V
    enc3(&wmapQ, Wh,   256,  768, 1,  512,  768ull * 512ull,  64, 128);  // QKV W [o][k]
    enc3(&wmapO, Woh,  256,  256, 1,  512,  256ull * 512ull,  64, 128);  // out W

    cudaFuncSetAttribute(gemm_h,  cudaFuncAttributeMaxDynamicSharedMemorySize, GH_SMEM_BYTES);
    cudaFuncSetAttribute(flash_h, cudaFuncAttributeMaxDynamicSharedMemorySize, FH_SMEM_BYTES);

    prep_k<<<1024, 256>>>(qkv_w, qkv_b, gamma, beta, rmean, rvar, out_w);
    gemm_h<<<dim3(8, 2, 16), 256, GH_SMEM_BYTES>>>(wmapQ, bp, x, nullptr, qkvh, nullptr, nullptr, 768);
    flash_h<<<dim3(8, 4, 16), 128, FH_SMEM_BYTES>>>(qkvh, avh, tmap);
    gemm_h<<<dim3(8, 2, 16), 256, GH_SMEM_BYTES>>>(wmapO, out_b, nullptr, avh, nullptr, (float*)d_out, x, 256);
}